// round 16
// baseline (speedup 1.0000x reference)
#include <cuda_runtime.h>
#include <cstdint>

#define NV_P   32
#define C_VX   0.16f
#define C_VY   0.16f
#define C_VZ   4.0f
#define C_XOFF 0.08f
#define C_YOFF -39.6f
#define C_ZOFF -1.0f
#define BN_EPS 1e-3f

#define VPB        96      // voxels per block == threads per block (k1)
#define K1_MAXB    1376
#define K3_BLOCKS  592
#define K3_THREADS 256
#define NSTAT      65
// stat layout: [0..9] M2 (xx,xy,xz,xw,yy,yz,yw,zz,zw,ww)  [10..13] m1(x,y,z,w)
//              [14..37] X[a][k]=m1[a]*q[k]  [38..58] Y tri = cnt*q[k]*q[l]  [59..64] cnt*q[k]
// q = (mx,my,mz,cx,cy,cz)

// -------- global scratch (allocation-free rule: __device__ globals) --------
__device__ float  g_part[NSTAT * K1_MAXB];   // [stat][block]
__device__ double g_stat[NSTAT];
__device__ float  g_ab[128];                 // |a|[0..63], b[64..127]
__device__ float4 g_mc4[131072];             // per-voxel (mx,my,mz,cx)
__device__ float2 g_c2[131072];              // per-voxel (cy,cz)

// ---------------- packed f32x2 helpers ----------------
__device__ __forceinline__ unsigned long long pk2(float lo, float hi) {
    unsigned long long r;
    asm("mov.b64 %0, {%1, %2};" : "=l"(r) : "f"(lo), "f"(hi));
    return r;
}
__device__ __forceinline__ void unpk2(unsigned long long x, float& lo, float& hi) {
    asm("mov.b64 {%0, %1}, %2;" : "=f"(lo), "=f"(hi) : "l"(x));
}
__device__ __forceinline__ unsigned long long fma2(unsigned long long a, unsigned long long b, unsigned long long c) {
    unsigned long long d;
    asm("fma.rn.f32x2 %0, %1, %2, %3;" : "=l"(d) : "l"(a), "l"(b), "l"(c));
    return d;
}
__device__ __forceinline__ unsigned long long add2(unsigned long long a, unsigned long long b) {
    unsigned long long d;
    asm("add.rn.f32x2 %0, %1, %2;" : "=l"(d) : "l"(a), "l"(b));
    return d;
}
__device__ __forceinline__ unsigned long long mul2(unsigned long long a, unsigned long long b) {
    unsigned long long d;
    asm("mul.rn.f32x2 %0, %1, %2;" : "=l"(d) : "l"(a), "l"(b));
    return d;
}
__device__ __forceinline__ uint32_t smem_u32(const void* p) {
    uint32_t a;
    asm("{ .reg .u64 t; cvta.to.shared.u64 t, %1; cvt.u32.u64 %0, t; }" : "=r"(a) : "l"(p));
    return a;
}
__device__ __forceinline__ void cpa16(uint32_t dst, const void* src) {
    asm volatile("cp.async.cg.shared.global [%0], [%1], 16;" :: "r"(dst), "l"(src) : "memory");
}
__device__ __forceinline__ float4 lds128f(uint32_t a) {
    float4 r;
    asm volatile("ld.shared.v4.f32 {%0,%1,%2,%3}, [%4];"
                 : "=f"(r.x), "=f"(r.y), "=f"(r.z), "=f"(r.w) : "r"(a));
    return r;
}

// ---------------- k1v2: voxel-per-thread raw-moment stats (R13 verbatim) ----------------
__global__ __launch_bounds__(VPB) void k1_stats(
    const float* __restrict__ vf, const int* __restrict__ vnp,
    const int* __restrict__ coords, int V)
{
    __shared__ __align__(16) unsigned char sbuf[VPB * NV_P * 16];   // 48 KB
    const int t = threadIdx.x;
    const int vbase = blockIdx.x * VPB;
    const uint32_t sb = smem_u32(sbuf);

    const int total = min(VPB, V - vbase) * NV_P;
    const float4* gsrc = reinterpret_cast<const float4*>(vf) + (size_t)vbase * NV_P;
#pragma unroll
    for (int k = 0; k < NV_P; k++) {
        int g = k * VPB + t;
        int gc = min(g, total - 1);
        int p = gc & 31, vv = gc >> 5;
        uint32_t dst = sb + ((uint32_t)((p * VPB + vv) << 4) ^ (uint32_t)((p & 7) << 4));
        if (g < total || gc != g)
            cpa16(dst, gsrc + gc);
    }
    asm volatile("cp.async.commit_group;" ::: "memory");
    asm volatile("cp.async.wait_group 0;" ::: "memory");
    __syncthreads();

    const int vg = vbase + t;
    const bool active = vg < V;
    int cnt = 1; int4 c4 = make_int4(0, 0, 0, 0);
    if (active) {
        cnt = vnp[vg];
        c4  = reinterpret_cast<const int4*>(coords)[vg];
    }

    unsigned long long M2a = 0ull, M2b = 0ull, M2c = 0ull, M2d = 0ull, M2e = 0ull;
    unsigned long long m1a = 0ull, m1b = 0ull, sxy = 0ull;
    float sz = 0.f;
#pragma unroll
    for (int p = 0; p < NV_P; p++) {
        uint32_t addr = sb + ((uint32_t)(((p * VPB + t) << 4)) ^ (uint32_t)((p & 7) << 4));
        float4 pt = lds128f(addr);
        unsigned long long pxy = pk2(pt.x, pt.y);
        unsigned long long pzw = pk2(pt.z, pt.w);
        sxy = add2(sxy, pxy);
        sz += pt.z;
        float mk = (p < cnt) ? 1.f : 0.f;
        unsigned long long mm  = pk2(mk, mk);
        unsigned long long mxy = mul2(pxy, mm);
        unsigned long long mzw = mul2(pzw, mm);
        m1a = add2(m1a, mxy);
        m1b = add2(m1b, mzw);
        unsigned long long bx  = pk2(pt.x, pt.x);
        unsigned long long by  = pk2(pt.y, pt.y);
        unsigned long long bz  = pk2(pt.z, pt.z);
        unsigned long long byw = pk2(pt.y, pt.w);
        M2a = fma2(bx, mxy, M2a);
        M2b = fma2(bx, mzw, M2b);
        M2c = fma2(by, mzw, M2c);
        M2d = fma2(bz, mzw, M2d);
        M2e = fma2(byw, mul2(byw, mm), M2e);
    }

    __syncthreads();
    float* red = reinterpret_cast<float*>(sbuf);   // [NSTAT][VPB+1]
    {
        float xx, xy; unpk2(M2a, xx, xy);
        float xz, xw; unpk2(M2b, xz, xw);
        float yz, yw; unpk2(M2c, yz, yw);
        float zz, zw; unpk2(M2d, zz, zw);
        float yy, ww; unpk2(M2e, yy, ww);
        float m1x, m1y; unpk2(m1a, m1x, m1y);
        float m1z, m1w; unpk2(m1b, m1z, m1w);
        float sx, sy; unpk2(sxy, sx, sy);
        float inv = 1.0f / (float)cnt;
        float mx = sx * inv, my = sy * inv, mz = sz * inv;
        float cx = (float)c4.w * C_VX + C_XOFF;
        float cy = (float)c4.z * C_VY + C_YOFF;
        float cz = (float)c4.y * C_VZ + C_ZOFF;
        if (active) {
            g_mc4[vg] = make_float4(mx, my, mz, cx);
            g_c2[vg]  = make_float2(cy, cz);
        }
        float q_[6]  = {mx, my, mz, cx, cy, cz};
        float m1_[4] = {m1x, m1y, m1z, m1w};
        float fc = (float)cnt;
#define STR(i, val) red[(i) * (VPB + 1) + t] = active ? (val) : 0.f
        STR(0, xx); STR(1, xy); STR(2, xz); STR(3, xw); STR(4, yy);
        STR(5, yz); STR(6, yw); STR(7, zz); STR(8, zw); STR(9, ww);
        STR(10, m1x); STR(11, m1y); STR(12, m1z); STR(13, m1w);
#pragma unroll
        for (int a = 0; a < 4; a++)
#pragma unroll
            for (int k = 0; k < 6; k++)
                STR(14 + a * 6 + k, m1_[a] * q_[k]);
        int idx = 38;
#pragma unroll
        for (int k = 0; k < 6; k++)
#pragma unroll
            for (int l = k; l < 6; l++) { STR(idx, fc * q_[k] * q_[l]); idx++; }
#pragma unroll
        for (int k = 0; k < 6; k++)
            STR(59 + k, fc * q_[k]);
#undef STR
    }
    __syncthreads();

    if (t < NSTAT) {
        float acc = 0.f;
#pragma unroll 8
        for (int i = 0; i < VPB; i++) acc += red[t * (VPB + 1) + i];
        g_part[t * K1_MAXB + blockIdx.x] = acc;
    }
}

// ---------------- kred: reduce per-block partials in double ----------------
__global__ void kred_stats(int nb) {
    int b = blockIdx.x;
    double s = 0.0;
    for (int i = threadIdx.x; i < nb; i += blockDim.x)
        s += (double)g_part[b * K1_MAXB + i];
    __shared__ double sd[256];
    sd[threadIdx.x] = s;
    __syncthreads();
    for (int off = 128; off; off >>= 1) {
        if (threadIdx.x < off) sd[threadIdx.x] += sd[threadIdx.x + off];
        __syncthreads();
    }
    if (threadIdx.x == 0) g_stat[b] = sd[0];
}

// ---------------- k2: parallel w^T S w — thread (o,i) owns one matrix row ----------------
__global__ void k2_coef(const float* __restrict__ W, const float* __restrict__ gamma,
                        const float* __restrict__ beta, double invN)
{
    __shared__ double Ssh[10][10];
    __shared__ double msh[10];
    const int t = threadIdx.x;

    // assemble S (55 threads, one upper-tri entry each) and mean vector (10 threads)
    if (t < 55) {
        int i = 0, tt = t;
        while (tt >= 10 - i) { tt -= 10 - i; i++; }
        int j = i + tt;
        const int amap[10] = {0, 1, 2, 3, 0, 1, 2, 0, 1, 2};
        const int m2off[4] = {0, 4, 7, 9};
        int a = amap[i], b = amap[j];
        int lo = a < b ? a : b, hi = a < b ? b : a;
        double S = g_stat[m2off[lo] + (hi - lo)];
        if (j >= 4) S -= g_stat[14 + a * 6 + (j - 4)];
        if (i >= 4) S -= g_stat[14 + b * 6 + (i - 4)];
        if (i >= 4 && j >= 4) {
            int k = i - 4, l = j - 4;
            int klo = k < l ? k : l, khi = k < l ? l : k;
            int yoff = klo * 6 - (klo * (klo - 1)) / 2;
            S += g_stat[38 + yoff + (khi - klo)];
        }
        Ssh[i][j] = S;
        Ssh[j][i] = S;
    }
    if (t >= 64 && t < 74) {
        int i = t - 64;
        const int amap[10] = {0, 1, 2, 3, 0, 1, 2, 0, 1, 2};
        msh[i] = g_stat[10 + amap[i]] - (i >= 4 ? g_stat[59 + (i - 4)] : 0.0);
    }
    __syncthreads();

    // 16 threads per channel: thread (o, i) computes row term w_o[i] * (S w_o)_i
    const int o = t >> 4;          // 0..63
    const int i = t & 15;          // row (active i<10)
    const float* wo = W + o * 10;
    double term = 0.0, mterm = 0.0;
    if (i < 10) {
        double wi = (double)wo[i];
        double acc = 0.0;
#pragma unroll
        for (int j = 0; j < 10; j++) acc += (double)wo[j] * Ssh[i][j];
        term  = wi * acc;
        mterm = wi * msh[i];
    }
    // reduce within the 16-lane group
#pragma unroll
    for (int off = 8; off; off >>= 1) {
        term  += __shfl_down_sync(0xffffffffu, term, off, 16);
        mterm += __shfl_down_sync(0xffffffffu, mterm, off, 16);
    }
    if (i == 0) {
        double mean = mterm * invN;
        double var  = term * invN - mean * mean;
        float a = gamma[o] * rsqrtf((float)var + BN_EPS);
        float b = beta[o] - (float)mean * a;
        g_ab[o]      = fabsf(a);
        g_ab[64 + o] = b;
    }
}

// ---------------- k3: point-pair packed max of s*(u.p); final affine+relu (R13 verbatim) ----------------
__global__ __launch_bounds__(K3_THREADS, 4) void k3_out(
    const float* __restrict__ vf, const int* __restrict__ vnp,
    const float* __restrict__ W, const float* __restrict__ gamma,
    float* __restrict__ out, int V)
{
    __shared__ __align__(16) float sh[8 * NV_P * 4];
    const int lane = threadIdx.x & 31;
    const int wib  = threadIdx.x >> 5;
    const int gw   = (blockIdx.x * blockDim.x + threadIdx.x) >> 5;
    const int nw   = (gridDim.x * blockDim.x) >> 5;
    float* msh = sh + wib * (NV_P * 4);

    const float* wA = W + (2 * lane) * 10;
    const float* wB = wA + 10;
    float sA = (gamma[2 * lane]     >= 0.f) ? 1.f : -1.f;
    float sB = (gamma[2 * lane + 1] >= 0.f) ? 1.f : -1.f;
    float uA0s = sA * (wA[0] + wA[4] + wA[7]);
    float uA1s = sA * (wA[1] + wA[5] + wA[8]);
    float uA2s = sA * (wA[2] + wA[6] + wA[9]);
    float uA3s = sA * wA[3];
    float uB0s = sB * (wB[0] + wB[4] + wB[7]);
    float uB1s = sB * (wB[1] + wB[5] + wB[8]);
    float uB2s = sB * (wB[2] + wB[6] + wB[9]);
    float uB3s = sB * wB[3];
    unsigned long long uA0 = pk2(uA0s, uA0s), uA1 = pk2(uA1s, uA1s);
    unsigned long long uA2 = pk2(uA2s, uA2s), uA3 = pk2(uA3s, uA3s);
    unsigned long long uB0 = pk2(uB0s, uB0s), uB1 = pk2(uB1s, uB1s);
    unsigned long long uB2 = pk2(uB2s, uB2s), uB3 = pk2(uB3s, uB3s);

    float2 av = reinterpret_cast<const float2*>(g_ab)[lane];
    float2 bv = reinterpret_cast<const float2*>(g_ab + 64)[lane];

    int v = gw;
    float4 pt; int cnt;
    if (v < V) {
        pt  = reinterpret_cast<const float4*>(vf)[v * NV_P + lane];
        cnt = vnp[v];
    }
    while (v < V) {
        int vn = v + nw;
        float4 ptn; int cntn;
        if (vn < V) {
            ptn  = reinterpret_cast<const float4*>(vf)[vn * NV_P + lane];
            cntn = vnp[vn];
        }
        float4 mc = g_mc4[v];
        float2 c2 = g_c2[v];
        float2 w4 = make_float2(wA[4], wB[4]);
        float2 w5 = make_float2(wA[5], wB[5]);
        float2 w6 = make_float2(wA[6], wB[6]);
        float2 w7 = make_float2(wA[7], wB[7]);
        float2 w8 = make_float2(wA[8], wB[8]);
        float2 w9 = make_float2(wA[9], wB[9]);

        __syncwarp();
        {
            float px = __shfl_xor_sync(0xffffffffu, pt.x, 1);
            float py = __shfl_xor_sync(0xffffffffu, pt.y, 1);
            float pz = __shfl_xor_sync(0xffffffffu, pt.z, 1);
            float pw = __shfl_xor_sync(0xffffffffu, pt.w, 1);
            float4 st;
            if (lane & 1) st = make_float4(pz, pt.z, pw, pt.w);
            else          st = make_float4(pt.x, px, pt.y, py);
            reinterpret_cast<float4*>(msh)[lane] = st;
        }
        __syncwarp();

        float mA = -3.402823466e38f, mB = -3.402823466e38f;
        const ulonglong2* pp = reinterpret_cast<const ulonglong2*>(msh);
        int npair = cnt >> 1;
        for (int k = 0; k < npair; k++) {
            ulonglong2 q = pp[2 * k];
            ulonglong2 r = pp[2 * k + 1];
            unsigned long long aA = mul2(q.x, uA0);
            unsigned long long aB = mul2(q.x, uB0);
            aA = fma2(q.y, uA1, aA);  aB = fma2(q.y, uB1, aB);
            aA = fma2(r.x, uA2, aA);  aB = fma2(r.x, uB2, aB);
            aA = fma2(r.y, uA3, aA);  aB = fma2(r.y, uB3, aB);
            float t0, t1;
            unpk2(aA, t0, t1); mA = fmaxf(mA, fmaxf(t0, t1));
            unpk2(aB, t0, t1); mB = fmaxf(mB, fmaxf(t0, t1));
        }
        if (cnt & 1) {
            ulonglong2 q = pp[2 * npair];
            ulonglong2 r = pp[2 * npair + 1];
            unsigned long long aA = mul2(q.x, uA0);
            unsigned long long aB = mul2(q.x, uB0);
            aA = fma2(q.y, uA1, aA);  aB = fma2(q.y, uB1, aB);
            aA = fma2(r.x, uA2, aA);  aB = fma2(r.x, uB2, aB);
            aA = fma2(r.y, uA3, aA);  aB = fma2(r.y, uB3, aB);
            float t0, t1;
            unpk2(aA, t0, t1); mA = fmaxf(mA, t0);
            unpk2(aB, t0, t1); mB = fmaxf(mB, t0);
        }

        float baA = -(mc.x * w4.x + mc.y * w5.x + mc.z * w6.x + mc.w * w7.x + c2.x * w8.x + c2.y * w9.x);
        float baB = -(mc.x * w4.y + mc.y * w5.y + mc.z * w6.y + mc.w * w7.y + c2.x * w8.y + c2.y * w9.y);
        float xA = mA + sA * baA;
        float xB = mB + sB * baB;
        if (cnt < NV_P) { xA = fmaxf(xA, 0.f); xB = fmaxf(xB, 0.f); }
        float r0o = fmaxf(fmaf(av.x, xA, bv.x), 0.f);
        float r1o = fmaxf(fmaf(av.y, xB, bv.y), 0.f);
        reinterpret_cast<float2*>(out)[v * 32 + lane] = make_float2(r0o, r1o);

        v = vn; pt = ptn; cnt = cntn;
    }
}

extern "C" void kernel_launch(void* const* d_in, const int* in_sizes, int n_in,
                              void* d_out, int out_size) {
    const float* vf     = (const float*)d_in[0];
    const int*   vnp    = (const int*)d_in[1];
    const int*   coords = (const int*)d_in[2];
    const float* W      = (const float*)d_in[3];
    const float* gamma  = (const float*)d_in[4];
    const float* beta   = (const float*)d_in[5];
    float* out = (float*)d_out;
    int V = in_sizes[1];   // voxel_num_points element count

    int nb = (V + VPB - 1) / VPB;
    k1_stats<<<nb, VPB>>>(vf, vnp, coords, V);
    kred_stats<<<NSTAT, 256>>>(nb);
    double invN = 1.0 / ((double)V * (double)NV_P);
    k2_coef<<<1, 1024>>>(W, gamma, beta, invN);
    k3_out<<<K3_BLOCKS, K3_THREADS>>>(vf, vnp, W, gamma, out, V);
}